// round 3
// baseline (speedup 1.0000x reference)
#include <cuda_runtime.h>
#include <cstdint>

#define N_NODES 100000
#define N_EDGES 3200000
#define D_FEAT  128
#define HIDDEN  16
#define NCLS    7
#define H2PAD   8   // padded layer-2 width (7 -> 8) for float4 loads

// ---- scratch (static __device__ arrays; no allocation allowed) ----
__device__ float d_dinv[N_NODES];
__device__ float d_g1  [N_NODES * HIDDEN];
__device__ float d_acc1[N_NODES * HIDDEN];
__device__ float d_g2  [N_NODES * H2PAD];
__device__ float d_acc2[N_NODES * H2PAD];

// ---------------- degree / dinv ----------------
__global__ void k_deg_init() {
    int n = blockIdx.x * blockDim.x + threadIdx.x;
    if (n < N_NODES) d_dinv[n] = 1.0f;   // self-loop weight
}

__global__ void k_deg_acc(const int* __restrict__ ei,
                          const float* __restrict__ ew) {
    int e = blockIdx.x * blockDim.x + threadIdx.x;
    if (e >= N_EDGES) return;
    int dst = ei[N_EDGES + e];
    atomicAdd(&d_dinv[dst], ew[e]);
}

__global__ void k_rsqrt() {
    int n = blockIdx.x * blockDim.x + threadIdx.x;
    if (n < N_NODES) d_dinv[n] = rsqrtf(d_dinv[n]);  // deg >= 1 always
}

// ---------------- layer 1 projection: g1 = (x @ W1) * dinv ----------------
__global__ void k_gemm1(const float* __restrict__ x,
                        const float* __restrict__ W1) {
    __shared__ float sW[D_FEAT * HIDDEN];
    for (int i = threadIdx.x; i < D_FEAT * HIDDEN; i += blockDim.x)
        sW[i] = W1[i];
    __syncthreads();

    int n = blockIdx.x * blockDim.x + threadIdx.x;
    if (n >= N_NODES) return;

    float acc[HIDDEN];
#pragma unroll
    for (int j = 0; j < HIDDEN; j++) acc[j] = 0.0f;

    const float4* xr = (const float4*)(x + (size_t)n * D_FEAT);
#pragma unroll 4
    for (int k4 = 0; k4 < D_FEAT / 4; k4++) {
        float4 v = xr[k4];
        int k = k4 * 4;
#pragma unroll
        for (int j = 0; j < HIDDEN; j++) {
            acc[j] = fmaf(v.x, sW[(k + 0) * HIDDEN + j],
                     fmaf(v.y, sW[(k + 1) * HIDDEN + j],
                     fmaf(v.z, sW[(k + 2) * HIDDEN + j],
                     fmaf(v.w, sW[(k + 3) * HIDDEN + j], acc[j]))));
        }
    }

    float di = d_dinv[n];
    float4* g = (float4*)(d_g1  + (size_t)n * HIDDEN);
    float4* a = (float4*)(d_acc1 + (size_t)n * HIDDEN);
#pragma unroll
    for (int q = 0; q < 4; q++) {
        float4 v = make_float4(acc[q*4+0]*di, acc[q*4+1]*di,
                               acc[q*4+2]*di, acc[q*4+3]*di);
        g[q] = v;   // message source values (pre-scaled by dinv[src])
        a[q] = v;   // accumulator initialized with self-loop term
    }
}

// ---------------- edge scatter, layer 1 (16 floats/edge) ----------------
__global__ void k_edge1(const int* __restrict__ ei,
                        const float* __restrict__ ew) {
    int e = blockIdx.x * blockDim.x + threadIdx.x;
    if (e >= N_EDGES) return;
    int src = ei[e];
    int dst = ei[N_EDGES + e];
    float w = ew[e];
    const float4* g = (const float4*)(d_g1 + (size_t)src * HIDDEN);
    float* a = d_acc1 + (size_t)dst * HIDDEN;
#pragma unroll
    for (int q = 0; q < 4; q++) {
        float4 v = g[q];
        atomicAdd(a + q * 4 + 0, v.x * w);
        atomicAdd(a + q * 4 + 1, v.y * w);
        atomicAdd(a + q * 4 + 2, v.z * w);
        atomicAdd(a + q * 4 + 3, v.w * w);
    }
}

// ---------------- layer-1 epilogue + layer-2 projection ----------------
__global__ void k_layer2(const float* __restrict__ b1,
                         const float* __restrict__ W2) {
    __shared__ float sW[HIDDEN * NCLS];
    __shared__ float sb1[HIDDEN];
    if (threadIdx.x < HIDDEN * NCLS) sW[threadIdx.x] = W2[threadIdx.x];
    if (threadIdx.x < HIDDEN)        sb1[threadIdx.x] = b1[threadIdx.x];
    __syncthreads();

    int n = blockIdx.x * blockDim.x + threadIdx.x;
    if (n >= N_NODES) return;

    float di = d_dinv[n];
    float h[HIDDEN];
    const float4* a = (const float4*)(d_acc1 + (size_t)n * HIDDEN);
#pragma unroll
    for (int q = 0; q < 4; q++) {
        float4 v = a[q];
        h[q*4+0] = fmaxf(v.x * di + sb1[q*4+0], 0.0f);
        h[q*4+1] = fmaxf(v.y * di + sb1[q*4+1], 0.0f);
        h[q*4+2] = fmaxf(v.z * di + sb1[q*4+2], 0.0f);
        h[q*4+3] = fmaxf(v.w * di + sb1[q*4+3], 0.0f);
    }

    float o[H2PAD];
#pragma unroll
    for (int c = 0; c < H2PAD; c++) o[c] = 0.0f;
#pragma unroll
    for (int j = 0; j < HIDDEN; j++) {
#pragma unroll
        for (int c = 0; c < NCLS; c++)
            o[c] = fmaf(h[j], sW[j * NCLS + c], o[c]);
    }

    float4* g  = (float4*)(d_g2  + (size_t)n * H2PAD);
    float4* ac = (float4*)(d_acc2 + (size_t)n * H2PAD);
#pragma unroll
    for (int q = 0; q < 2; q++) {
        float4 v = make_float4(o[q*4+0]*di, o[q*4+1]*di, o[q*4+2]*di, o[q*4+3]*di);
        g[q] = v;
        ac[q] = v;
    }
}

// ---------------- edge scatter, layer 2 (8 floats/edge, 7 useful) ----------------
__global__ void k_edge2(const int* __restrict__ ei,
                        const float* __restrict__ ew) {
    int e = blockIdx.x * blockDim.x + threadIdx.x;
    if (e >= N_EDGES) return;
    int src = ei[e];
    int dst = ei[N_EDGES + e];
    float w = ew[e];
    const float4* g = (const float4*)(d_g2 + (size_t)src * H2PAD);
    float* a = d_acc2 + (size_t)dst * H2PAD;
    float4 v0 = g[0];
    float4 v1 = g[1];
    atomicAdd(a + 0, v0.x * w);
    atomicAdd(a + 1, v0.y * w);
    atomicAdd(a + 2, v0.z * w);
    atomicAdd(a + 3, v0.w * w);
    atomicAdd(a + 4, v1.x * w);
    atomicAdd(a + 5, v1.y * w);
    atomicAdd(a + 6, v1.z * w);
    // col 7 is padding — skip
}

// ---------------- layer-2 epilogue: log_softmax ----------------
__global__ void k_out(const float* __restrict__ b2,
                      float* __restrict__ out) {
    int n = blockIdx.x * blockDim.x + threadIdx.x;
    if (n >= N_NODES) return;
    float di = d_dinv[n];
    float v[NCLS];
#pragma unroll
    for (int c = 0; c < NCLS; c++)
        v[c] = d_acc2[(size_t)n * H2PAD + c] * di + b2[c];
    float m = v[0];
#pragma unroll
    for (int c = 1; c < NCLS; c++) m = fmaxf(m, v[c]);
    float s = 0.0f;
#pragma unroll
    for (int c = 0; c < NCLS; c++) s += expf(v[c] - m);
    float lse = m + logf(s);
#pragma unroll
    for (int c = 0; c < NCLS; c++)
        out[(size_t)n * NCLS + c] = v[c] - lse;
}

extern "C" void kernel_launch(void* const* d_in, const int* in_sizes, int n_in,
                              void* d_out, int out_size) {
    const float* x  = (const float*)d_in[0];
    const int*   ei = (const int*)d_in[1];    // edge_index: int32 (JAX x64 disabled)
    const float* ew = (const float*)d_in[2];
    const float* W1 = (const float*)d_in[3];
    const float* b1 = (const float*)d_in[4];
    const float* W2 = (const float*)d_in[5];
    const float* b2 = (const float*)d_in[6];
    float* out = (float*)d_out;

    const int TB = 256;
    const int nodeGrid = (N_NODES + TB - 1) / TB;
    const int edgeGrid = (N_EDGES + TB - 1) / TB;

    k_deg_init<<<nodeGrid, TB>>>();
    k_deg_acc<<<edgeGrid, TB>>>(ei, ew);
    k_rsqrt<<<nodeGrid, TB>>>();
    k_gemm1<<<nodeGrid, TB>>>(x, W1);
    k_edge1<<<edgeGrid, TB>>>(ei, ew);
    k_layer2<<<nodeGrid, TB>>>(b1, W2);
    k_edge2<<<edgeGrid, TB>>>(ei, ew);
    k_out<<<nodeGrid, TB>>>(b2, out);
}

// round 4
// speedup vs baseline: 2.0994x; 2.0994x over previous
#include <cuda_runtime.h>
#include <cstdint>

#define N_NODES 100000
#define N_EDGES 3200000
#define D_FEAT  128
#define HIDDEN  16
#define NCLS    7
#define H2PAD   8   // padded layer-2 width (7 -> 8) for float4 ops

// ---- scratch (static __device__ arrays; no allocation allowed) ----
__device__ float d_dinv[N_NODES];
__device__ float d_g1  [N_NODES * HIDDEN];
__device__ float d_acc1[N_NODES * HIDDEN];
__device__ float d_g2  [N_NODES * H2PAD];
__device__ float d_acc2[N_NODES * H2PAD];

// vector reduction: 4 floats, one L2 atomic op
__device__ __forceinline__ void red_v4(float* p, float a, float b, float c, float d) {
    unsigned long long gp = __cvta_generic_to_global(p);
    asm volatile("red.global.v4.f32.add [%0], {%1,%2,%3,%4};"
                 :: "l"(gp), "f"(a), "f"(b), "f"(c), "f"(d) : "memory");
}

// ---------------- degree / dinv ----------------
__global__ void k_deg_init() {
    int n = blockIdx.x * blockDim.x + threadIdx.x;
    if (n < N_NODES) d_dinv[n] = 1.0f;   // self-loop weight
}

__global__ void k_deg_acc(const int* __restrict__ ei,
                          const float* __restrict__ ew) {
    int e = blockIdx.x * blockDim.x + threadIdx.x;
    if (e >= N_EDGES) return;
    atomicAdd(&d_dinv[ei[N_EDGES + e]], ew[e]);
}

__global__ void k_rsqrt() {
    int n = blockIdx.x * blockDim.x + threadIdx.x;
    if (n < N_NODES) d_dinv[n] = rsqrtf(d_dinv[n]);  // deg >= 1 always
}

// ---------------- layer 1 projection: g1 = (x @ W1) * dinv ----------------
// Block = 256 threads = 256 nodes. x staged through smem, fully coalesced.
#define KCHUNK 32
__global__ void __launch_bounds__(256) k_gemm1(const float* __restrict__ x,
                                               const float* __restrict__ W1) {
    __shared__ float sW[D_FEAT * HIDDEN];          // 8 KB
    __shared__ float sx[256][KCHUNK + 1];          // 33.8 KB, pad -> conflict-free
    for (int i = threadIdx.x; i < D_FEAT * HIDDEN; i += blockDim.x)
        sW[i] = W1[i];

    int tid = threadIdx.x;
    int n0 = blockIdx.x * 256;
    int n  = n0 + tid;
    int nrows = min(256, N_NODES - n0);            // rows this block owns

    float acc[HIDDEN];
#pragma unroll
    for (int j = 0; j < HIDDEN; j++) acc[j] = 0.0f;

    for (int c = 0; c < D_FEAT / KCHUNK; c++) {
        __syncthreads();
        // coalesced load: 8 consecutive threads read one 128B row-chunk
        // idx covers nrows*KCHUNK floats as float4s
        int nvec = nrows * (KCHUNK / 4);           // float4 count
        for (int idx = tid; idx < nvec; idx += 256) {
            int r = idx >> 3;                      // KCHUNK/4 = 8 vecs per row
            int q = idx & 7;
            float4 v = *(const float4*)(x + (size_t)(n0 + r) * D_FEAT + c * KCHUNK + q * 4);
            sx[r][q * 4 + 0] = v.x;
            sx[r][q * 4 + 1] = v.y;
            sx[r][q * 4 + 2] = v.z;
            sx[r][q * 4 + 3] = v.w;
        }
        __syncthreads();
        if (n < N_NODES) {
#pragma unroll
            for (int kk = 0; kk < KCHUNK; kk++) {
                float v = sx[tid][kk];
                const float* wrow = &sW[(c * KCHUNK + kk) * HIDDEN];
#pragma unroll
                for (int j = 0; j < HIDDEN; j++)
                    acc[j] = fmaf(v, wrow[j], acc[j]);
            }
        }
    }

    if (n >= N_NODES) return;
    float di = d_dinv[n];
    float4* g = (float4*)(d_g1  + (size_t)n * HIDDEN);
    float4* a = (float4*)(d_acc1 + (size_t)n * HIDDEN);
#pragma unroll
    for (int q = 0; q < 4; q++) {
        float4 v = make_float4(acc[q*4+0]*di, acc[q*4+1]*di,
                               acc[q*4+2]*di, acc[q*4+3]*di);
        g[q] = v;   // message source values (pre-scaled by dinv[src])
        a[q] = v;   // accumulator initialized with self-loop term
    }
}

// ---------------- edge scatter, layer 1 (4 vector reds/edge) ----------------
__global__ void k_edge1(const int* __restrict__ ei,
                        const float* __restrict__ ew) {
    int e = blockIdx.x * blockDim.x + threadIdx.x;
    if (e >= N_EDGES) return;
    int src = ei[e];
    int dst = ei[N_EDGES + e];
    float w = ew[e];
    const float4* g = (const float4*)(d_g1 + (size_t)src * HIDDEN);
    float* a = d_acc1 + (size_t)dst * HIDDEN;
#pragma unroll
    for (int q = 0; q < 4; q++) {
        float4 v = g[q];
        red_v4(a + q * 4, v.x * w, v.y * w, v.z * w, v.w * w);
    }
}

// ---------------- layer-1 epilogue + layer-2 projection ----------------
__global__ void k_layer2(const float* __restrict__ b1,
                         const float* __restrict__ W2) {
    __shared__ float sW[HIDDEN * NCLS];
    __shared__ float sb1[HIDDEN];
    if (threadIdx.x < HIDDEN * NCLS) sW[threadIdx.x] = W2[threadIdx.x];
    if (threadIdx.x < HIDDEN)        sb1[threadIdx.x] = b1[threadIdx.x];
    __syncthreads();

    int n = blockIdx.x * blockDim.x + threadIdx.x;
    if (n >= N_NODES) return;

    float di = d_dinv[n];
    float h[HIDDEN];
    const float4* a = (const float4*)(d_acc1 + (size_t)n * HIDDEN);
#pragma unroll
    for (int q = 0; q < 4; q++) {
        float4 v = a[q];
        h[q*4+0] = fmaxf(v.x * di + sb1[q*4+0], 0.0f);
        h[q*4+1] = fmaxf(v.y * di + sb1[q*4+1], 0.0f);
        h[q*4+2] = fmaxf(v.z * di + sb1[q*4+2], 0.0f);
        h[q*4+3] = fmaxf(v.w * di + sb1[q*4+3], 0.0f);
    }

    float o[H2PAD];
#pragma unroll
    for (int c = 0; c < H2PAD; c++) o[c] = 0.0f;   // o[7] stays exactly 0
#pragma unroll
    for (int j = 0; j < HIDDEN; j++) {
#pragma unroll
        for (int c = 0; c < NCLS; c++)
            o[c] = fmaf(h[j], sW[j * NCLS + c], o[c]);
    }

    float4* g  = (float4*)(d_g2  + (size_t)n * H2PAD);
    float4* ac = (float4*)(d_acc2 + (size_t)n * H2PAD);
#pragma unroll
    for (int q = 0; q < 2; q++) {
        float4 v = make_float4(o[q*4+0]*di, o[q*4+1]*di, o[q*4+2]*di, o[q*4+3]*di);
        g[q] = v;
        ac[q] = v;
    }
}

// ---------------- edge scatter, layer 2 (2 vector reds/edge) ----------------
__global__ void k_edge2(const int* __restrict__ ei,
                        const float* __restrict__ ew) {
    int e = blockIdx.x * blockDim.x + threadIdx.x;
    if (e >= N_EDGES) return;
    int src = ei[e];
    int dst = ei[N_EDGES + e];
    float w = ew[e];
    const float4* g = (const float4*)(d_g2 + (size_t)src * H2PAD);
    float* a = d_acc2 + (size_t)dst * H2PAD;
    float4 v0 = g[0];
    float4 v1 = g[1];
    red_v4(a + 0, v0.x * w, v0.y * w, v0.z * w, v0.w * w);
    red_v4(a + 4, v1.x * w, v1.y * w, v1.z * w, v1.w * w);  // lane 7 adds 0.0
}

// ---------------- layer-2 epilogue: log_softmax ----------------
__global__ void k_out(const float* __restrict__ b2,
                      float* __restrict__ out) {
    int n = blockIdx.x * blockDim.x + threadIdx.x;
    if (n >= N_NODES) return;
    float di = d_dinv[n];
    float v[NCLS];
    const float4* a = (const float4*)(d_acc2 + (size_t)n * H2PAD);
    float4 p0 = a[0], p1 = a[1];
    v[0] = p0.x * di + b2[0];
    v[1] = p0.y * di + b2[1];
    v[2] = p0.z * di + b2[2];
    v[3] = p0.w * di + b2[3];
    v[4] = p1.x * di + b2[4];
    v[5] = p1.y * di + b2[5];
    v[6] = p1.z * di + b2[6];
    float m = v[0];
#pragma unroll
    for (int c = 1; c < NCLS; c++) m = fmaxf(m, v[c]);
    float s = 0.0f;
#pragma unroll
    for (int c = 0; c < NCLS; c++) s += expf(v[c] - m);
    float lse = m + logf(s);
#pragma unroll
    for (int c = 0; c < NCLS; c++)
        out[(size_t)n * NCLS + c] = v[c] - lse;
}

extern "C" void kernel_launch(void* const* d_in, const int* in_sizes, int n_in,
                              void* d_out, int out_size) {
    const float* x  = (const float*)d_in[0];
    const int*   ei = (const int*)d_in[1];    // edge_index: int32
    const float* ew = (const float*)d_in[2];
    const float* W1 = (const float*)d_in[3];
    const float* b1 = (const float*)d_in[4];
    const float* W2 = (const float*)d_in[5];
    const float* b2 = (const float*)d_in[6];
    float* out = (float*)d_out;

    const int TB = 256;
    const int nodeGrid = (N_NODES + TB - 1) / TB;
    const int edgeGrid = (N_EDGES + TB - 1) / TB;

    k_deg_init<<<nodeGrid, TB>>>();
    k_deg_acc<<<edgeGrid, TB>>>(ei, ew);
    k_rsqrt<<<nodeGrid, TB>>>();
    k_gemm1<<<nodeGrid, TB>>>(x, W1);
    k_edge1<<<edgeGrid, TB>>>(ei, ew);
    k_layer2<<<nodeGrid, TB>>>(b1, W2);
    k_edge2<<<edgeGrid, TB>>>(ei, ew);
    k_out<<<nodeGrid, TB>>>(b2, out);
}